// round 15
// baseline (speedup 1.0000x reference)
#include <cuda_runtime.h>
#include <cstdint>
#include <cstddef>

#define CB 4
#define CE 512
#define CP 1536
#define CH 32
#define CHK 8
#define CD 128
#define CS 2048
#define TQ 64
#define TK 48
#define NTHREADS 128
#define SCALE_L2E 0.12751741814489405f
#define NEG_INF -1e30f

// scratch planes padded 16KB: ragged last tile may read up to 16 rows past CS
#define SCR_PLANE (16u * 1024 * 1024 + 16384u)
__device__ __align__(256) unsigned char g_scr[2ull * SCR_PLANE];  // K, V fp16 swizzled

// smem: 3 stages x 24KB (K 12KB + V 12KB). Q staged through stage 0 then overwritten.
#define STAGE_STRIDE 24576
#define VOFF 12288
#define SMEM_BYTES 73728

__device__ __forceinline__ uint32_t swz(uint32_t row, uint32_t byteCol) {
    return (row << 8) + (byteCol ^ ((row & 7) << 4));
}
__device__ __forceinline__ uint32_t smem_u32(const void* p) {
    uint32_t a;
    asm("{ .reg .u64 t; cvta.to.shared.u64 t, %1; cvt.u32.u64 %0, t; }"
        : "=r"(a) : "l"(p));
    return a;
}
__device__ __forceinline__ float ex2(float x) {
    float y;
    asm("ex2.approx.ftz.f32 %0, %1;" : "=f"(y) : "f"(x));
    return y;
}
__device__ __forceinline__ uint32_t packh(float x0, float x1) {
    uint32_t r;
    asm("cvt.rn.f16x2.f32 %0, %1, %2;" : "=r"(r) : "f"(x1), "f"(x0));
    return r;
}
__device__ __forceinline__ void ldsm4(uint32_t r[4], uint32_t addr) {
    asm volatile("ldmatrix.sync.aligned.m8n8.x4.shared.b16 {%0,%1,%2,%3}, [%4];"
                 : "=r"(r[0]), "=r"(r[1]), "=r"(r[2]), "=r"(r[3]) : "r"(addr));
}
__device__ __forceinline__ void ldsm4t(uint32_t r[4], uint32_t addr) {
    asm volatile("ldmatrix.sync.aligned.m8n8.x4.trans.shared.b16 {%0,%1,%2,%3}, [%4];"
                 : "=r"(r[0]), "=r"(r[1]), "=r"(r[2]), "=r"(r[3]) : "r"(addr));
}
__device__ __forceinline__ void mma16816h(float c[4], const uint32_t a[4],
                                          uint32_t b0, uint32_t b1) {
    asm volatile(
        "mma.sync.aligned.m16n8k16.row.col.f32.f16.f16.f32 "
        "{%0,%1,%2,%3}, {%4,%5,%6,%7}, {%8,%9}, {%0,%1,%2,%3};"
        : "+f"(c[0]), "+f"(c[1]), "+f"(c[2]), "+f"(c[3])
        : "r"(a[0]), "r"(a[1]), "r"(a[2]), "r"(a[3]), "r"(b0), "r"(b1));
}
__device__ __forceinline__ void cpa16(uint32_t dst, const void* src) {
    asm volatile("cp.async.cg.shared.global [%0], [%1], 16;"
                 :: "r"(dst), "l"(src) : "memory");
}
#define CPA_COMMIT() asm volatile("cp.async.commit_group;" ::: "memory")
#define CPA_WAIT1()  asm volatile("cp.async.wait_group 1;" ::: "memory")

// ---------------- prep kernel: fp32 K/V -> swizzled fp16 planes ----------------
__global__ __launch_bounds__(256)
void prep_kv(const float* __restrict__ gk,  const float* __restrict__ gv,
             const float* __restrict__ gkc, const float* __restrict__ gvc) {
    const int task = blockIdx.x * 256 + threadIdx.x;
    const int g   = task & 15;
    const int s   = (task >> 4) & (CS - 1);
    const int khb = task >> 15;
    const int kh  = khb & 7, b = khb >> 3;

    const float *kr, *vr;
    if (s < CP) {
        size_t o = ((size_t)(b * CP + s) * CHK + kh) * CD;
        kr = gkc + o; vr = gvc + o;
    } else {
        size_t o = ((size_t)(b * CE + (s - CP)) * CHK + kh) * CD;
        kr = gk + o; vr = gv + o;
    }
    const int col = g * 8;
    const uint32_t dst = (((uint32_t)khb * CS + s) << 8) + ((g * 16) ^ ((s & 7) << 4));

    float4 x0 = *(const float4*)(kr + col);
    float4 x1 = *(const float4*)(kr + col + 4);
    uint4 p;
    p.x = packh(x0.x, x0.y); p.y = packh(x0.z, x0.w);
    p.z = packh(x1.x, x1.y); p.w = packh(x1.z, x1.w);
    *(uint4*)(g_scr + 0ull * SCR_PLANE + dst) = p;

    x0 = *(const float4*)(vr + col);
    x1 = *(const float4*)(vr + col + 4);
    p.x = packh(x0.x, x0.y); p.y = packh(x0.z, x0.w);
    p.z = packh(x1.x, x1.y); p.w = packh(x1.z, x1.w);
    *(uint4*)(g_scr + 1ull * SCR_PLANE + dst) = p;
}

// ---------------- main attention kernel (3 CTAs/SM, TK=48, 1 barrier/tile) ----------------
__global__ __launch_bounds__(NTHREADS, 3)
void radix_extend_hmma(const float* __restrict__ gq, float* __restrict__ out) {
    extern __shared__ char smem[];
    const uint32_t sb = smem_u32(smem);
    const int t = threadIdx.x, w = t >> 5, lane = t & 31;
    const int e0 = blockIdx.x * TQ, h = blockIdx.y, b = blockIdx.z;
    const int khb = b * CHK + (h >> 2);
    const int ntiles = (CP + e0 + TQ + TK - 1) / TK;   // 34..43

    // ---- stage Q through stage-0 smem: fold scale*log2e, fp16, swizzled ----
    {
        const int qrow = t >> 1;
        const int cbase = (t & 1) * 64;
        const float* qr = gq + ((size_t)(b * CE + e0 + qrow) * CH + h) * CD;
        #pragma unroll
        for (int g = 0; g < 8; ++g) {
            int colf = cbase + 8 * g;
            float4 x0 = *(const float4*)(qr + colf);
            float4 x1 = *(const float4*)(qr + colf + 4);
            uint4 hi;
            hi.x = packh(x0.x * SCALE_L2E, x0.y * SCALE_L2E);
            hi.y = packh(x0.z * SCALE_L2E, x0.w * SCALE_L2E);
            hi.z = packh(x1.x * SCALE_L2E, x1.y * SCALE_L2E);
            hi.w = packh(x1.z * SCALE_L2E, x1.w * SCALE_L2E);
            *(uint4*)(smem + swz(qrow, (uint32_t)colf * 2)) = hi;
        }
    }
    __syncthreads();

    // ---- persistent Q fragments ----
    const uint32_t qrow = 16 * w + (lane & 7) + 8 * ((lane >> 3) & 1);
    const uint32_t qbc0 = 16 * (lane >> 4);
    uint32_t qh[8][4];
    #pragma unroll
    for (int kk = 0; kk < 8; ++kk)
        ldsm4(qh[kk], sb + swz(qrow, qbc0 + kk * 32));
    __syncthreads();   // Q region free -> becomes stage 0

    // prologue: prefetch tiles 0,1 (one commit group each)
    #pragma unroll
    for (int pre = 0; pre < 2; ++pre) {
        const uint32_t tile_off = (((uint32_t)(khb * CS) + pre * TK) << 8);
        const uint32_t dstb = sb + pre * STAGE_STRIDE;
        #pragma unroll
        for (int u = 0; u < 12; ++u) {
            int idx = u * NTHREADS + t;          // 0..1535
            int plane = idx >= 768;
            int off = (idx - plane * 768) * 16;
            cpa16(dstb + plane * VOFF + off,
                  g_scr + (size_t)plane * SCR_PLANE + tile_off + off);
        }
        CPA_COMMIT();
    }

    const uint32_t rB  = (lane & 7) + 8 * (lane >> 4);
    const uint32_t bcB = 16 * ((lane >> 3) & 1);
    const uint32_t rV  = (lane & 7) + 8 * ((lane >> 3) & 1);
    const uint32_t bcV = 16 * (lane >> 4);

    const int row0 = 16 * w + (lane >> 2);
    const int lim0 = CP + e0 + row0;
    const int lim1 = lim0 + 8;
    float m0 = NEG_INF, m1 = NEG_INF;
    float l0 = 0.0f, l1 = 0.0f;          // per-lane partial sums

    float o[16][4];
    #pragma unroll
    for (int j = 0; j < 16; ++j)
        #pragma unroll
        for (int c = 0; c < 4; ++c) o[j][c] = 0.0f;

    int stg = 0;   // kt % 3
    for (int kt = 0; kt < ntiles; ++kt) {
        const int s0 = kt * TK;
        const uint32_t stage = sb + stg * STAGE_STRIDE;

        CPA_WAIT1();        // own copies of tile kt done (only kt+1's group pending)
        __syncthreads();    // all threads' copies visible; reads of stage (kt-1)%3 done

        // prefetch tile kt+2 into stage (kt+2)%3 == (kt-1)%3 (safe per barrier above)
        if (kt + 2 < ntiles) {
            int stg2 = stg + 2 >= 3 ? stg - 1 : stg + 2;
            const uint32_t tile_off = (((uint32_t)(khb * CS) + (s0 + 2 * TK)) << 8);
            const uint32_t dstb = sb + stg2 * STAGE_STRIDE;
            #pragma unroll
            for (int u = 0; u < 12; ++u) {
                int idx = u * NTHREADS + t;
                int plane = idx >= 768;
                int off = (idx - plane * 768) * 16;
                cpa16(dstb + plane * VOFF + off,
                      g_scr + (size_t)plane * SCR_PLANE + tile_off + off);
            }
        }
        CPA_COMMIT();       // uniform group counting

        // ---- phase 1: S = Qh Kh^T (48 keys), double-buffered K fragments ----
        float s[6][4];
        #pragma unroll
        for (int nt = 0; nt < 6; ++nt)
            #pragma unroll
            for (int c = 0; c < 4; ++c) s[nt][c] = 0.0f;

        uint32_t kf[2][4];
        ldsm4(kf[0], stage + swz(rB, bcB));

        #pragma unroll
        for (int it = 0; it < 24; ++it) {
            const int kk = it >> 1 >> 0; // placeholder; real mapping below
            (void)kk;
            const int kki = it / 3, ng = it - kki * 3;
            const int cur = it & 1, nxt = cur ^ 1;
            if (it + 1 < 24) {
                const int kk2 = (it + 1) / 3, ng2 = (it + 1) - kk2 * 3;
                ldsm4(kf[nxt], stage + swz(16 * ng2 + rB, bcB + kk2 * 32));
            }
            mma16816h(s[2 * ng],     qh[kki], kf[cur][0], kf[cur][1]);
            mma16816h(s[2 * ng + 1], qh[kki], kf[cur][2], kf[cur][3]);
        }

        // ---- mask (ragged/causal tiles) ----
        if (s0 + TK - 1 > CP + e0) {
            const int j0 = s0 + 2 * (lane & 3);
            #pragma unroll
            for (int nt = 0; nt < 6; ++nt) {
                int jj = j0 + 8 * nt;
                if (jj     > lim0) s[nt][0] = NEG_INF;
                if (jj + 1 > lim0) s[nt][1] = NEG_INF;
                if (jj     > lim1) s[nt][2] = NEG_INF;
                if (jj + 1 > lim1) s[nt][3] = NEG_INF;
            }
        }

        // ---- online softmax (log2 domain; partial l) ----
        float mt0 = NEG_INF, mt1 = NEG_INF;
        #pragma unroll
        for (int nt = 0; nt < 6; ++nt) {
            mt0 = fmaxf(mt0, fmaxf(s[nt][0], s[nt][1]));
            mt1 = fmaxf(mt1, fmaxf(s[nt][2], s[nt][3]));
        }
        mt0 = fmaxf(mt0, __shfl_xor_sync(0xffffffffu, mt0, 1));
        mt0 = fmaxf(mt0, __shfl_xor_sync(0xffffffffu, mt0, 2));
        mt1 = fmaxf(mt1, __shfl_xor_sync(0xffffffffu, mt1, 1));
        mt1 = fmaxf(mt1, __shfl_xor_sync(0xffffffffu, mt1, 2));

        float mn0 = fmaxf(m0, mt0), mn1 = fmaxf(m1, mt1);
        float sc0 = ex2(m0 - mn0), sc1 = ex2(m1 - mn1);
        m0 = mn0; m1 = mn1;

        float ps0 = 0.0f, ps1 = 0.0f;
        #pragma unroll
        for (int nt = 0; nt < 6; ++nt) {
            s[nt][0] = ex2(s[nt][0] - mn0);
            s[nt][1] = ex2(s[nt][1] - mn0);
            s[nt][2] = ex2(s[nt][2] - mn1);
            s[nt][3] = ex2(s[nt][3] - mn1);
            ps0 += s[nt][0] + s[nt][1];
            ps1 += s[nt][2] + s[nt][3];
        }
        l0 = l0 * sc0 + ps0;
        l1 = l1 * sc1 + ps1;

        #pragma unroll
        for (int j = 0; j < 16; ++j) {
            o[j][0] *= sc0; o[j][1] *= sc0;
            o[j][2] *= sc1; o[j][3] *= sc1;
        }

        // ---- phase 2: O += Ph Vh (48 keys = 3 kk-groups), double-buffered V ----
        uint32_t vf[2][4];
        ldsm4t(vf[0], stage + VOFF + swz(rV, bcV));

        uint32_t ah[4];
        ah[0] = packh(s[0][0], s[0][1]);
        ah[1] = packh(s[0][2], s[0][3]);
        ah[2] = packh(s[1][0], s[1][1]);
        ah[3] = packh(s[1][2], s[1][3]);

        #pragma unroll
        for (int it = 0; it < 24; ++it) {
            const int kk = it >> 3, ng = it & 7;
            const int cur = it & 1, nxt = cur ^ 1;
            if (it + 1 < 24) {
                const int kk2 = (it + 1) >> 3, ng2 = (it + 1) & 7;
                ldsm4t(vf[nxt], stage + VOFF + swz(16 * kk2 + rV, bcV + 32 * ng2));
            }
            mma16816h(o[2 * ng],     ah, vf[cur][0], vf[cur][1]);
            mma16816h(o[2 * ng + 1], ah, vf[cur][2], vf[cur][3]);
            if (ng == 7 && kk < 2) {
                ah[0] = packh(s[2 * kk + 2][0], s[2 * kk + 2][1]);
                ah[1] = packh(s[2 * kk + 2][2], s[2 * kk + 2][3]);
                ah[2] = packh(s[2 * kk + 3][0], s[2 * kk + 3][1]);
                ah[3] = packh(s[2 * kk + 3][2], s[2 * kk + 3][3]);
            }
        }

        stg = (stg + 1 == 3) ? 0 : stg + 1;
    }

    // ---- epilogue: reduce l partials, normalize, store ----
    l0 += __shfl_xor_sync(0xffffffffu, l0, 1);
    l0 += __shfl_xor_sync(0xffffffffu, l0, 2);
    l1 += __shfl_xor_sync(0xffffffffu, l1, 1);
    l1 += __shfl_xor_sync(0xffffffffu, l1, 2);

    const float inv0 = 1.0f / l0, inv1 = 1.0f / l1;
    float* orow0 = out + (size_t)(b * CE + e0 + row0) * (CH * CD) + h * CD;
    float* orow1 = orow0 + (size_t)8 * (CH * CD);
    const int dc = 2 * (lane & 3);
    #pragma unroll
    for (int j = 0; j < 16; ++j) {
        float2 f0 = make_float2(o[j][0] * inv0, o[j][1] * inv0);
        float2 f1 = make_float2(o[j][2] * inv1, o[j][3] * inv1);
        *(float2*)(orow0 + 8 * j + dc) = f0;
        *(float2*)(orow1 + 8 * j + dc) = f1;
    }
}

extern "C" void kernel_launch(void* const* d_in, const int* in_sizes, int n_in,
                              void* d_out, int out_size) {
    (void)in_sizes; (void)n_in; (void)out_size;
    const float* q  = (const float*)d_in[0];
    const float* k  = (const float*)d_in[1];
    const float* v  = (const float*)d_in[2];
    const float* kc = (const float*)d_in[3];
    const float* vc = (const float*)d_in[4];
    float* out = (float*)d_out;

    prep_kv<<<(CB * CHK * CS * 16) / 256, 256>>>(k, v, kc, vc);

    cudaFuncSetAttribute(radix_extend_hmma,
                         cudaFuncAttributeMaxDynamicSharedMemorySize, SMEM_BYTES);
    dim3 grid(CE / TQ, CH, CB);   // (8, 32, 4) = 1024 CTAs
    radix_extend_hmma<<<grid, NTHREADS, SMEM_BYTES>>>(q, out);
}

// round 16
// speedup vs baseline: 1.1030x; 1.1030x over previous
#include <cuda_runtime.h>
#include <cstdint>
#include <cstddef>

#define CB 4
#define CE 512
#define CP 1536
#define CH 32
#define CHK 8
#define CD 128
#define CS 2048
#define TQ 64
#define TK 64
#define NTHREADS 128
#define SCALE_L2E 0.12751741814489405f
#define NEG_INF -1e30f

#define SCR_PLANE (16u * 1024 * 1024)
__device__ __align__(256) unsigned char g_scr[2ull * SCR_PLANE];  // K, V fp16 swizzled

// smem: Q plane (16KB) + 3-stage K/V buffers (32KB each)
#define OFF_QH 0
#define OFF_ST 16384
#define STAGE_STRIDE 32768
#define PLANE_STRIDE 16384
#define SMEM_BYTES 114688

__device__ __forceinline__ uint32_t swz(uint32_t row, uint32_t byteCol) {
    return (row << 8) + (byteCol ^ ((row & 7) << 4));
}
__device__ __forceinline__ uint32_t smem_u32(const void* p) {
    uint32_t a;
    asm("{ .reg .u64 t; cvta.to.shared.u64 t, %1; cvt.u32.u64 %0, t; }"
        : "=r"(a) : "l"(p));
    return a;
}
__device__ __forceinline__ float ex2(float x) {
    float y;
    asm("ex2.approx.ftz.f32 %0, %1;" : "=f"(y) : "f"(x));
    return y;
}
__device__ __forceinline__ uint32_t packh(float x0, float x1) {
    uint32_t r;
    asm("cvt.rn.f16x2.f32 %0, %1, %2;" : "=r"(r) : "f"(x1), "f"(x0));
    return r;
}
__device__ __forceinline__ void ldsm4(uint32_t r[4], uint32_t addr) {
    asm volatile("ldmatrix.sync.aligned.m8n8.x4.shared.b16 {%0,%1,%2,%3}, [%4];"
                 : "=r"(r[0]), "=r"(r[1]), "=r"(r[2]), "=r"(r[3]) : "r"(addr));
}
__device__ __forceinline__ void ldsm4t(uint32_t r[4], uint32_t addr) {
    asm volatile("ldmatrix.sync.aligned.m8n8.x4.trans.shared.b16 {%0,%1,%2,%3}, [%4];"
                 : "=r"(r[0]), "=r"(r[1]), "=r"(r[2]), "=r"(r[3]) : "r"(addr));
}
__device__ __forceinline__ void mma16816h(float c[4], const uint32_t a[4],
                                          uint32_t b0, uint32_t b1) {
    asm volatile(
        "mma.sync.aligned.m16n8k16.row.col.f32.f16.f16.f32 "
        "{%0,%1,%2,%3}, {%4,%5,%6,%7}, {%8,%9}, {%0,%1,%2,%3};"
        : "+f"(c[0]), "+f"(c[1]), "+f"(c[2]), "+f"(c[3])
        : "r"(a[0]), "r"(a[1]), "r"(a[2]), "r"(a[3]), "r"(b0), "r"(b1));
}
__device__ __forceinline__ void cpa16(uint32_t dst, const void* src) {
    asm volatile("cp.async.cg.shared.global [%0], [%1], 16;"
                 :: "r"(dst), "l"(src) : "memory");
}
#define CPA_COMMIT() asm volatile("cp.async.commit_group;" ::: "memory")
#define CPA_WAIT1()  asm volatile("cp.async.wait_group 1;" ::: "memory")

// ---------------- prep kernel: fp32 K/V -> swizzled fp16 planes ----------------
__global__ __launch_bounds__(256)
void prep_kv(const float* __restrict__ gk,  const float* __restrict__ gv,
             const float* __restrict__ gkc, const float* __restrict__ gvc) {
    const int task = blockIdx.x * 256 + threadIdx.x;
    const int g   = task & 15;
    const int s   = (task >> 4) & (CS - 1);
    const int khb = task >> 15;
    const int kh  = khb & 7, b = khb >> 3;

    const float *kr, *vr;
    if (s < CP) {
        size_t o = ((size_t)(b * CP + s) * CHK + kh) * CD;
        kr = gkc + o; vr = gvc + o;
    } else {
        size_t o = ((size_t)(b * CE + (s - CP)) * CHK + kh) * CD;
        kr = gk + o; vr = gv + o;
    }
    const int col = g * 8;
    const uint32_t dst = (((uint32_t)khb * CS + s) << 8) + ((g * 16) ^ ((s & 7) << 4));

    float4 x0 = *(const float4*)(kr + col);
    float4 x1 = *(const float4*)(kr + col + 4);
    uint4 p;
    p.x = packh(x0.x, x0.y); p.y = packh(x0.z, x0.w);
    p.z = packh(x1.x, x1.y); p.w = packh(x1.z, x1.w);
    *(uint4*)(g_scr + 0ull * SCR_PLANE + dst) = p;

    x0 = *(const float4*)(vr + col);
    x1 = *(const float4*)(vr + col + 4);
    p.x = packh(x0.x, x0.y); p.y = packh(x0.z, x0.w);
    p.z = packh(x1.x, x1.y); p.w = packh(x1.z, x1.w);
    *(uint4*)(g_scr + 1ull * SCR_PLANE + dst) = p;
}

// ---------------- main attention kernel (2 CTAs/SM, depth-3 fragment pipe) ----------------
__global__ __launch_bounds__(NTHREADS, 2)
void radix_extend_hmma(const float* __restrict__ gq, float* __restrict__ out) {
    extern __shared__ char smem[];
    const uint32_t sb = smem_u32(smem);
    const int t = threadIdx.x, w = t >> 5, lane = t & 31;
    const int e0 = blockIdx.x * TQ, h = blockIdx.y, b = blockIdx.z;
    const int khb = b * CHK + (h >> 2);
    const int ntiles = (CP + e0 + TQ) / TK;   // >= 25

    // prologue: prefetch tiles 0,1 (one commit group each)
    #pragma unroll
    for (int pre = 0; pre < 2; ++pre) {
        const uint32_t tile_off = (((uint32_t)khb * CS + pre * TK) << 8);
        const uint32_t dstb = sb + OFF_ST + pre * STAGE_STRIDE;
        #pragma unroll
        for (int u = 0; u < 16; ++u) {
            int idx = u * NTHREADS + t;
            int plane = idx >> 10;
            int off = (idx & 1023) * 16;
            cpa16(dstb + plane * PLANE_STRIDE + off,
                  g_scr + (size_t)plane * SCR_PLANE + tile_off + off);
        }
        CPA_COMMIT();
    }

    // ---- load Q tile: fold scale*log2e, quantize fp16, swizzled store ----
    {
        const int qrow = t >> 1;
        const int cbase = (t & 1) * 64;
        const float* qr = gq + ((size_t)(b * CE + e0 + qrow) * CH + h) * CD;
        #pragma unroll
        for (int g = 0; g < 8; ++g) {
            int colf = cbase + 8 * g;
            float4 x0 = *(const float4*)(qr + colf);
            float4 x1 = *(const float4*)(qr + colf + 4);
            uint4 hi;
            hi.x = packh(x0.x * SCALE_L2E, x0.y * SCALE_L2E);
            hi.y = packh(x0.z * SCALE_L2E, x0.w * SCALE_L2E);
            hi.z = packh(x1.x * SCALE_L2E, x1.y * SCALE_L2E);
            hi.w = packh(x1.z * SCALE_L2E, x1.w * SCALE_L2E);
            *(uint4*)(smem + OFF_QH + swz(qrow, (uint32_t)colf * 2)) = hi;
        }
    }
    __syncthreads();

    // ---- persistent Q fragments ----
    const uint32_t qrow = 16 * w + (lane & 7) + 8 * ((lane >> 3) & 1);
    const uint32_t qbc0 = 16 * (lane >> 4);
    uint32_t qh[8][4];
    #pragma unroll
    for (int kk = 0; kk < 8; ++kk)
        ldsm4(qh[kk], sb + OFF_QH + swz(qrow, qbc0 + kk * 32));

    const uint32_t rB  = (lane & 7) + 8 * (lane >> 4);
    const uint32_t bcB = 16 * ((lane >> 3) & 1);
    const uint32_t rV  = (lane & 7) + 8 * ((lane >> 3) & 1);
    const uint32_t bcV = 16 * (lane >> 4);

    const int row0 = 16 * w + (lane >> 2);
    const int lim0 = CP + e0 + row0;
    const int lim1 = lim0 + 8;
    float m0 = NEG_INF, m1 = NEG_INF;
    float l0 = 0.0f, l1 = 0.0f;          // per-lane partial sums

    float o[16][4];
    #pragma unroll
    for (int j = 0; j < 16; ++j)
        #pragma unroll
        for (int c = 0; c < 4; ++c) o[j][c] = 0.0f;

    int stg = 0;   // kt % 3
    for (int kt = 0; kt < ntiles; ++kt) {
        const int s0 = kt * TK;
        const uint32_t stage = sb + OFF_ST + stg * STAGE_STRIDE;

        CPA_WAIT1();        // own copies of tile kt done (only kt+1's group may remain)
        __syncthreads();    // everyone's tile-kt copies visible; reads of stage (kt-1)%3 done

        // hoisted K-fragment preloads (it = 0,1,2) — latency hidden behind cp.async issue
        uint32_t kf[3][4];
        ldsm4(kf[0], stage + swz(rB, bcB));                    // kk=0, ng=0
        ldsm4(kf[1], stage + swz(16 + rB, bcB));               // kk=0, ng=1
        ldsm4(kf[2], stage + swz(32 + rB, bcB));               // kk=0, ng=2

        // prefetch tile kt+2 into stage (kt+2)%3 == (kt-1)%3 (safe per barrier above)
        if (kt + 2 < ntiles) {
            int stg2 = stg + 2 >= 3 ? stg - 1 : stg + 2;
            const uint32_t tile_off = (((uint32_t)khb * CS + (s0 + 2 * TK)) << 8);
            const uint32_t dstb = sb + OFF_ST + stg2 * STAGE_STRIDE;
            #pragma unroll
            for (int u = 0; u < 16; ++u) {
                int idx = u * NTHREADS + t;
                int plane = idx >> 10;
                int off = (idx & 1023) * 16;
                cpa16(dstb + plane * PLANE_STRIDE + off,
                      g_scr + (size_t)plane * SCR_PLANE + tile_off + off);
            }
        }
        CPA_COMMIT();       // uniform group counting

        // ---- phase 1: S = Qh Kh^T, depth-3 K-fragment pipeline ----
        float s[8][4];
        #pragma unroll
        for (int nt = 0; nt < 8; ++nt)
            #pragma unroll
            for (int c = 0; c < 4; ++c) s[nt][c] = 0.0f;

        #pragma unroll
        for (int it = 0; it < 32; ++it) {
            const int kk = it >> 2, ng = it & 3;
            const int cur = it % 3;
            mma16816h(s[2 * ng],     qh[kk], kf[cur][0], kf[cur][1]);
            mma16816h(s[2 * ng + 1], qh[kk], kf[cur][2], kf[cur][3]);
            if (it + 3 < 32) {      // reload the slot just consumed with fragment it+3
                const int kk2 = (it + 3) >> 2, ng2 = (it + 3) & 3;
                ldsm4(kf[cur], stage + swz(16 * ng2 + rB, bcB + kk2 * 32));
            }
        }

        // hoisted V-fragment preloads (it = 0,1,2) — latency hidden behind softmax
        uint32_t vf[3][4];
        ldsm4t(vf[0], stage + PLANE_STRIDE + swz(rV, bcV));            // kk=0, ng=0
        ldsm4t(vf[1], stage + PLANE_STRIDE + swz(rV, bcV + 32));       // kk=0, ng=1
        ldsm4t(vf[2], stage + PLANE_STRIDE + swz(rV, bcV + 64));       // kk=0, ng=2

        // ---- mask (only last 2 tiles) ----
        if (s0 + TK - 1 > CP + e0) {
            const int j0 = s0 + 2 * (lane & 3);
            #pragma unroll
            for (int nt = 0; nt < 8; ++nt) {
                int jj = j0 + 8 * nt;
                if (jj     > lim0) s[nt][0] = NEG_INF;
                if (jj + 1 > lim0) s[nt][1] = NEG_INF;
                if (jj     > lim1) s[nt][2] = NEG_INF;
                if (jj + 1 > lim1) s[nt][3] = NEG_INF;
            }
        }

        // ---- online softmax (log2 domain; partial l) ----
        float mt0 = NEG_INF, mt1 = NEG_INF;
        #pragma unroll
        for (int nt = 0; nt < 8; ++nt) {
            mt0 = fmaxf(mt0, fmaxf(s[nt][0], s[nt][1]));
            mt1 = fmaxf(mt1, fmaxf(s[nt][2], s[nt][3]));
        }
        mt0 = fmaxf(mt0, __shfl_xor_sync(0xffffffffu, mt0, 1));
        mt0 = fmaxf(mt0, __shfl_xor_sync(0xffffffffu, mt0, 2));
        mt1 = fmaxf(mt1, __shfl_xor_sync(0xffffffffu, mt1, 1));
        mt1 = fmaxf(mt1, __shfl_xor_sync(0xffffffffu, mt1, 2));

        float mn0 = fmaxf(m0, mt0), mn1 = fmaxf(m1, mt1);
        float sc0 = ex2(m0 - mn0), sc1 = ex2(m1 - mn1);
        m0 = mn0; m1 = mn1;

        float ps0 = 0.0f, ps1 = 0.0f;
        #pragma unroll
        for (int nt = 0; nt < 8; ++nt) {
            s[nt][0] = ex2(s[nt][0] - mn0);
            s[nt][1] = ex2(s[nt][1] - mn0);
            s[nt][2] = ex2(s[nt][2] - mn1);
            s[nt][3] = ex2(s[nt][3] - mn1);
            ps0 += s[nt][0] + s[nt][1];
            ps1 += s[nt][2] + s[nt][3];
        }
        l0 = l0 * sc0 + ps0;    // sc uniform within quad -> partial-l exact
        l1 = l1 * sc1 + ps1;

        #pragma unroll
        for (int j = 0; j < 16; ++j) {
            o[j][0] *= sc0; o[j][1] *= sc0;
            o[j][2] *= sc1; o[j][3] *= sc1;
        }

        // ---- phase 2: O += Ph Vh, depth-3 V-fragment pipeline ----
        uint32_t ah[4];
        ah[0] = packh(s[0][0], s[0][1]);
        ah[1] = packh(s[0][2], s[0][3]);
        ah[2] = packh(s[1][0], s[1][1]);
        ah[3] = packh(s[1][2], s[1][3]);

        #pragma unroll
        for (int it = 0; it < 32; ++it) {
            const int kk = it >> 3, ng = it & 7;
            const int cur = it % 3;
            mma16816h(o[2 * ng],     ah, vf[cur][0], vf[cur][1]);
            mma16816h(o[2 * ng + 1], ah, vf[cur][2], vf[cur][3]);
            if (it + 3 < 32) {
                const int kk2 = (it + 3) >> 3, ng2 = (it + 3) & 7;
                ldsm4t(vf[cur], stage + PLANE_STRIDE + swz(16 * kk2 + rV, bcV + 32 * ng2));
            }
            if (ng == 7 && kk < 3) {
                ah[0] = packh(s[2 * kk + 2][0], s[2 * kk + 2][1]);
                ah[1] = packh(s[2 * kk + 2][2], s[2 * kk + 2][3]);
                ah[2] = packh(s[2 * kk + 3][0], s[2 * kk + 3][1]);
                ah[3] = packh(s[2 * kk + 3][2], s[2 * kk + 3][3]);
            }
        }

        stg = (stg + 1 == 3) ? 0 : stg + 1;
    }

    // ---- epilogue: reduce l partials, normalize, store ----
    l0 += __shfl_xor_sync(0xffffffffu, l0, 1);
    l0 += __shfl_xor_sync(0xffffffffu, l0, 2);
    l1 += __shfl_xor_sync(0xffffffffu, l1, 1);
    l1 += __shfl_xor_sync(0xffffffffu, l1, 2);

    const float inv0 = 1.0f / l0, inv1 = 1.0f / l1;
    float* orow0 = out + (size_t)(b * CE + e0 + row0) * (CH * CD) + h * CD;
    float* orow1 = orow0 + (size_t)8 * (CH * CD);
    const int dc = 2 * (lane & 3);
    #pragma unroll
    for (int j = 0; j < 16; ++j) {
        float2 f0 = make_float2(o[j][0] * inv0, o[j][1] * inv0);
        float2 f1 = make_float2(o[j][2] * inv1, o[j][3] * inv1);
        *(float2*)(orow0 + 8 * j + dc) = f0;
        *(float2*)(orow1 + 8 * j + dc) = f1;
    }
}

extern "C" void kernel_launch(void* const* d_in, const int* in_sizes, int n_in,
                              void* d_out, int out_size) {
    (void)in_sizes; (void)n_in; (void)out_size;
    const float* q  = (const float*)d_in[0];
    const float* k  = (const float*)d_in[1];
    const float* v  = (const float*)d_in[2];
    const float* kc = (const float*)d_in[3];
    const float* vc = (const float*)d_in[4];
    float* out = (float*)d_out;

    prep_kv<<<(CB * CHK * CS * 16) / 256, 256>>>(k, v, kc, vc);

    cudaFuncSetAttribute(radix_extend_hmma,
                         cudaFuncAttributeMaxDynamicSharedMemorySize, SMEM_BYTES);
    dim3 grid(CE / TQ, CH, CB);   // (8, 32, 4) = 1024 CTAs
    radix_extend_hmma<<<grid, NTHREADS, SMEM_BYTES>>>(q, out);
}